// round 7
// baseline (speedup 1.0000x reference)
#include <cuda_runtime.h>

// Problem constants
#define NN   1024
#define PP   4
#define SS   12
#define MM   64
#define KK   16
#define MK   80
#define NSYM 13
#define NBLK (NN*PP)              // 4096
#define NSYMTOT (NBLK*NSYM)       // 53248

// Output layout: [info_pilot | info_sig | H_true | noise_pwr]
#define IP_OFF 0
#define IS_OFF (NN*PP*MM*2)                  //   524288
#define HT_OFF (IS_OFF + NN*PP*SS*MM*2)      //  6815744
#define NP_OFF (HT_OFF + NN*PP*MM*2)         //  7340032

#define NOISE_PWR 1.5625e-4f                 // 1/(64*10^2)
#define CNOISE 8.8388347648e-3f              // sqrt(noise_pwr/2)
#define SQ2H 0.70710678f

// W64^j for j = 0..7  (higher powers via log-depth chain)
__constant__ float2 c_W8[8] = {
    { 1.00000000f,  0.00000000f}, { 0.99518473f, -0.09801714f},
    { 0.98078528f, -0.19509032f}, { 0.95694034f, -0.29028468f},
    { 0.92387953f, -0.38268343f}, { 0.88192126f, -0.47139674f},
    { 0.83146961f, -0.55557023f}, { 0.77301045f, -0.63439328f}
};

// amp[l] = sqrt(0.5 * exp(-l/4) / sum_l exp(-l/4))
__constant__ float c_amp[8] = {
    0.35764563f, 0.31562116f, 0.27853470f, 0.24580602f,
    0.21692305f, 0.19143393f, 0.16893985f, 0.14908891f
};

__device__ __forceinline__ float2 cadd(float2 a, float2 b) { return make_float2(a.x+b.x, a.y+b.y); }
__device__ __forceinline__ float2 csub(float2 a, float2 b) { return make_float2(a.x-b.x, a.y-b.y); }
__device__ __forceinline__ float2 mul_mi(float2 z) { return make_float2(z.y, -z.x); }   // -i*z
__device__ __forceinline__ float2 cmul(float2 a, float2 b) {
    return make_float2(fmaf(a.x, b.x, -a.y*b.y), fmaf(a.x, b.y, a.y*b.x));
}
__device__ __forceinline__ float2 w81(float2 z) { return make_float2(SQ2H*(z.x+z.y), SQ2H*(z.y-z.x)); }
__device__ __forceinline__ float2 w83(float2 z) { return make_float2(SQ2H*(z.y-z.x), -SQ2H*(z.x+z.y)); }

// X[k] = sum_n x[n] * W8^{nk}  (radix-2 DIT)
__device__ __forceinline__ void dft8(const float2* x, float2* X) {
    float2 t0 = cadd(x[0], x[4]), t1 = csub(x[0], x[4]);
    float2 t2 = cadd(x[2], x[6]), t3 = csub(x[2], x[6]);
    float2 E0 = cadd(t0, t2), E2 = csub(t0, t2);
    float2 mt3 = mul_mi(t3);
    float2 E1 = cadd(t1, mt3), E3 = csub(t1, mt3);

    float2 s0 = cadd(x[1], x[5]), s1 = csub(x[1], x[5]);
    float2 s2 = cadd(x[3], x[7]), s3 = csub(x[3], x[7]);
    float2 O0 = cadd(s0, s2), O2 = csub(s0, s2);
    float2 ms3 = mul_mi(s3);
    float2 O1 = cadd(s1, ms3), O3 = csub(s1, ms3);

    float2 o1 = w81(O1);
    float2 o2 = mul_mi(O2);
    float2 o3 = w83(O3);

    X[0] = cadd(E0, O0); X[4] = csub(E0, O0);
    X[1] = cadd(E1, o1); X[5] = csub(E1, o1);
    X[2] = cadd(E2, o2); X[6] = csub(E2, o2);
    X[3] = cadd(E3, o3); X[7] = csub(E3, o3);
}

__global__ __launch_bounds__(128, 9) void ofdm_fused(
    const float* __restrict__ x,
    const float* __restrict__ pilot_raw,
    const float* __restrict__ cof_unit,
    const float* __restrict__ noise_unit,
    float* __restrict__ out)
{
    __shared__ float2 Z[16][8][9];            // padded transpose buffer

    const int tid  = threadIdx.x;
    const int g    = blockIdx.x * 128 + tid;
    const int gsym = g >> 3;                  // 0..53247
    const int lb   = g & 7;
    const int grp  = tid >> 3;
    const int blk  = gsym / NSYM;
    const int sym  = gsym - blk * NSYM;
    const bool isp = (sym == 0);
    // 8-lane group mask: exactly the lanes that share this thread's isp value
    const unsigned gmask = 0xFFu << ((tid & 31) & ~7);

    // ---- noise loads (post-CP samples only), issued first for MLP ----
    const float2* nb = (const float2*)noise_unit
                     + (size_t)blk * NSYM * MK + sym * MK + KK + lb;
    float2 in[8];
    #pragma unroll
    for (int a = 0; a < 8; a++) in[a] = nb[a * 8];

    // ---- powers p[c] = W64^{lb*c}, log-depth chain from one constant ----
    float2 p1 = c_W8[lb];
    float2 p2 = cmul(p1, p1);
    float2 p3 = cmul(p2, p1);
    float2 p4 = cmul(p2, p2);
    float2 p5 = cmul(p4, p1);
    float2 p6 = cmul(p3, p3);
    float2 p7 = cmul(p4, p3);

    // ---- noise FFT64 stage 1: DFT8 over a, then twiddle W64^{lb*c} ----
    {
        float2 u[8];
        dft8(in, u);
        u[1] = cmul(u[1], p1); u[2] = cmul(u[2], p2); u[3] = cmul(u[3], p3);
        u[4] = cmul(u[4], p4); u[5] = cmul(u[5], p5); u[6] = cmul(u[6], p6);
        u[7] = cmul(u[7], p7);
        #pragma unroll
        for (int c = 0; c < 8; c++) Z[grp][lb][c] = u[c];
    }

    // ---- H in-thread: Hv[d] = DFT8_l( amp_l*cof_l*W64^{l*lb} ) ----
    float2 Hv[8];
    {
        const float4* cp4 = (const float4*)((const float2*)cof_unit + blk * 8);
        float4 q0 = cp4[0], q1 = cp4[1], q2 = cp4[2], q3 = cp4[3];
        float2 e[8];
        e[0] = make_float2(c_amp[0]*q0.x, c_amp[0]*q0.y);
        e[1] = cmul(make_float2(c_amp[1]*q0.z, c_amp[1]*q0.w), p1);
        e[2] = cmul(make_float2(c_amp[2]*q1.x, c_amp[2]*q1.y), p2);
        e[3] = cmul(make_float2(c_amp[3]*q1.z, c_amp[3]*q1.w), p3);
        e[4] = cmul(make_float2(c_amp[4]*q2.x, c_amp[4]*q2.y), p4);
        e[5] = cmul(make_float2(c_amp[5]*q2.z, c_amp[5]*q2.w), p5);
        e[6] = cmul(make_float2(c_amp[6]*q3.x, c_amp[6]*q3.y), p6);
        e[7] = cmul(make_float2(c_amp[7]*q3.z, c_amp[7]*q3.w), p7);
        dft8(e, Hv);                          // Hv[d] = H[lb + 8d]
    }

    // ---- sym-0 group stores H_true while it's live ----
    if (isp) {
        float2* hq = (float2*)(out + HT_OFF) + blk * 64;
        #pragma unroll
        for (int d = 0; d < 8; d++) hq[lb + 8 * d] = Hv[d];
    }
    if (g == 0) out[NP_OFF] = NOISE_PWR;

    // ---- signal loads ----
    const float2* sp = isp ? ((const float2*)pilot_raw + blk * 64)
                           : ((const float2*)x + ((size_t)blk * SS + (sym - 1)) * 64);
    float2 sv[8];
    #pragma unroll
    for (int d = 0; d < 8; d++) sv[d] = sp[lb + 8 * d];

    if (isp) {
        // group-local reduction: mask matches exactly the executing lanes
        float pw = 0.f;
        #pragma unroll
        for (int d = 0; d < 8; d++) pw += sv[d].x * sv[d].x + sv[d].y * sv[d].y;
        pw += __shfl_xor_sync(gmask, pw, 1);
        pw += __shfl_xor_sync(gmask, pw, 2);
        pw += __shfl_xor_sync(gmask, pw, 4);
        float scale = 8.0f * rsqrtf(pw);      // sqrt(PWR/2)/sqrt(mean(pilot_raw^2))
        #pragma unroll
        for (int d = 0; d < 8; d++) { sv[d].x *= scale; sv[d].y *= scale; }
    }

    // ---- fold H*sig in place: Hv dies here, before Nf materializes ----
    #pragma unroll
    for (int d = 0; d < 8; d++) sv[d] = cmul(Hv[d], sv[d]);

    __syncwarp();

    // ---- transpose read + stage 2 ----
    float2 z[8];
    #pragma unroll
    for (int b = 0; b < 8; b++) z[b] = Z[grp][b][lb];
    float2 Nf[8];
    dft8(z, Nf);                              // Nf[d] = N[lb + 8d]

    // ---- epilogue: out = (H*sig) + CNOISE * noiseFFT ----
    float2* op = isp ? ((float2*)(out + IP_OFF) + blk * 64)
                     : ((float2*)(out + IS_OFF) + ((size_t)blk * SS + (sym - 1)) * 64);
    #pragma unroll
    for (int d = 0; d < 8; d++) {
        float2 r;
        r.x = fmaf(CNOISE, Nf[d].x, sv[d].x);
        r.y = fmaf(CNOISE, Nf[d].y, sv[d].y);
        op[lb + 8 * d] = r;
    }
}

extern "C" void kernel_launch(void* const* d_in, const int* in_sizes, int n_in,
                              void* d_out, int out_size) {
    const float* x          = (const float*)d_in[0];
    const float* pilot_raw  = (const float*)d_in[1];
    const float* cof_unit   = (const float*)d_in[2];
    const float* noise_unit = (const float*)d_in[3];
    float* out = (float*)d_out;

    ofdm_fused<<<NSYMTOT * 8 / 128, 128>>>(x, pilot_raw, cof_unit, noise_unit, out);
}

// round 8
// speedup vs baseline: 1.0043x; 1.0043x over previous
#include <cuda_runtime.h>

// Problem constants
#define NN   1024
#define PP   4
#define SS   12
#define MM   64
#define KK   16
#define MK   80
#define NSYM 13
#define NBLK (NN*PP)              // 4096
#define NSYMTOT (NBLK*NSYM)       // 53248

// Output layout: [info_pilot | info_sig | H_true | noise_pwr]
#define IP_OFF 0
#define IS_OFF (NN*PP*MM*2)                  //   524288
#define HT_OFF (IS_OFF + NN*PP*SS*MM*2)      //  6815744
#define NP_OFF (HT_OFF + NN*PP*MM*2)         //  7340032

#define NOISE_PWR 1.5625e-4f                 // 1/(64*10^2)
#define CNOISE 8.8388347648e-3f              // sqrt(noise_pwr/2)
#define SQ2H 0.70710678f

// W64^j for j = 0..7  (higher powers via log-depth chain)
__constant__ float2 c_W8[8] = {
    { 1.00000000f,  0.00000000f}, { 0.99518473f, -0.09801714f},
    { 0.98078528f, -0.19509032f}, { 0.95694034f, -0.29028468f},
    { 0.92387953f, -0.38268343f}, { 0.88192126f, -0.47139674f},
    { 0.83146961f, -0.55557023f}, { 0.77301045f, -0.63439328f}
};

// amp[l] = sqrt(0.5 * exp(-l/4) / sum_l exp(-l/4))
__constant__ float c_amp[8] = {
    0.35764563f, 0.31562116f, 0.27853470f, 0.24580602f,
    0.21692305f, 0.19143393f, 0.16893985f, 0.14908891f
};

__device__ __forceinline__ float2 cadd(float2 a, float2 b) { return make_float2(a.x+b.x, a.y+b.y); }
__device__ __forceinline__ float2 csub(float2 a, float2 b) { return make_float2(a.x-b.x, a.y-b.y); }
__device__ __forceinline__ float2 mul_mi(float2 z) { return make_float2(z.y, -z.x); }   // -i*z
__device__ __forceinline__ float2 cmul(float2 a, float2 b) {
    return make_float2(fmaf(a.x, b.x, -a.y*b.y), fmaf(a.x, b.y, a.y*b.x));
}
__device__ __forceinline__ float2 w81(float2 z) { return make_float2(SQ2H*(z.x+z.y), SQ2H*(z.y-z.x)); }
__device__ __forceinline__ float2 w83(float2 z) { return make_float2(SQ2H*(z.y-z.x), -SQ2H*(z.x+z.y)); }

// X[k] = sum_n x[n] * W8^{nk}  (radix-2 DIT)
__device__ __forceinline__ void dft8(const float2* x, float2* X) {
    float2 t0 = cadd(x[0], x[4]), t1 = csub(x[0], x[4]);
    float2 t2 = cadd(x[2], x[6]), t3 = csub(x[2], x[6]);
    float2 E0 = cadd(t0, t2), E2 = csub(t0, t2);
    float2 mt3 = mul_mi(t3);
    float2 E1 = cadd(t1, mt3), E3 = csub(t1, mt3);

    float2 s0 = cadd(x[1], x[5]), s1 = csub(x[1], x[5]);
    float2 s2 = cadd(x[3], x[7]), s3 = csub(x[3], x[7]);
    float2 O0 = cadd(s0, s2), O2 = csub(s0, s2);
    float2 ms3 = mul_mi(s3);
    float2 O1 = cadd(s1, ms3), O3 = csub(s1, ms3);

    float2 o1 = w81(O1);
    float2 o2 = mul_mi(O2);
    float2 o3 = w83(O3);

    X[0] = cadd(E0, O0); X[4] = csub(E0, O0);
    X[1] = cadd(E1, o1); X[5] = csub(E1, o1);
    X[2] = cadd(E2, o2); X[6] = csub(E2, o2);
    X[3] = cadd(E3, o3); X[7] = csub(E3, o3);
}

__device__ __forceinline__ float2 ldcs2(const float2* p) {
    float2 v = __ldcs(p);
    return v;
}
__device__ __forceinline__ void stcs2(float2* p, float2 v) {
    __stcs(p, v);
}

__global__ __launch_bounds__(128, 10) void ofdm_fused(
    const float* __restrict__ x,
    const float* __restrict__ pilot_raw,
    const float* __restrict__ cof_unit,
    const float* __restrict__ noise_unit,
    float* __restrict__ out)
{
    __shared__ float2 Z[16][8][9];            // padded transpose buffer

    const int tid  = threadIdx.x;
    const int g    = blockIdx.x * 128 + tid;
    const int gsym = g >> 3;                  // 0..53247
    const int lb   = g & 7;
    const int grp  = tid >> 3;
    const int blk  = gsym / NSYM;
    const int sym  = gsym - blk * NSYM;
    const bool isp = (sym == 0);
    // 8-lane group mask: exactly the lanes that share this thread's isp value
    const unsigned gmask = 0xFFu << ((tid & 31) & ~7);

    // ---- noise loads (post-CP, streaming/evict-first), issued first for MLP ----
    const float2* nb = (const float2*)noise_unit
                     + (size_t)blk * NSYM * MK + sym * MK + KK + lb;
    float2 in[8];
    #pragma unroll
    for (int a = 0; a < 8; a++) in[a] = ldcs2(nb + a * 8);

    // ---- powers p[c] = W64^{lb*c}, log-depth chain from one constant ----
    float2 p1 = c_W8[lb];
    float2 p2 = cmul(p1, p1);
    float2 p3 = cmul(p2, p1);
    float2 p4 = cmul(p2, p2);
    float2 p5 = cmul(p4, p1);
    float2 p6 = cmul(p3, p3);
    float2 p7 = cmul(p4, p3);

    // ---- noise FFT64 stage 1: DFT8 over a, then twiddle W64^{lb*c} ----
    {
        float2 u[8];
        dft8(in, u);
        u[1] = cmul(u[1], p1); u[2] = cmul(u[2], p2); u[3] = cmul(u[3], p3);
        u[4] = cmul(u[4], p4); u[5] = cmul(u[5], p5); u[6] = cmul(u[6], p6);
        u[7] = cmul(u[7], p7);
        #pragma unroll
        for (int c = 0; c < 8; c++) Z[grp][lb][c] = u[c];
    }

    // ---- H in-thread: Hv[d] = DFT8_l( amp_l*cof_l*W64^{l*lb} ) ----
    float2 Hv[8];
    {
        const float4* cp4 = (const float4*)((const float2*)cof_unit + blk * 8);
        float4 q0 = cp4[0], q1 = cp4[1], q2 = cp4[2], q3 = cp4[3];
        float2 e[8];
        e[0] = make_float2(c_amp[0]*q0.x, c_amp[0]*q0.y);
        e[1] = cmul(make_float2(c_amp[1]*q0.z, c_amp[1]*q0.w), p1);
        e[2] = cmul(make_float2(c_amp[2]*q1.x, c_amp[2]*q1.y), p2);
        e[3] = cmul(make_float2(c_amp[3]*q1.z, c_amp[3]*q1.w), p3);
        e[4] = cmul(make_float2(c_amp[4]*q2.x, c_amp[4]*q2.y), p4);
        e[5] = cmul(make_float2(c_amp[5]*q2.z, c_amp[5]*q2.w), p5);
        e[6] = cmul(make_float2(c_amp[6]*q3.x, c_amp[6]*q3.y), p6);
        e[7] = cmul(make_float2(c_amp[7]*q3.z, c_amp[7]*q3.w), p7);
        dft8(e, Hv);                          // Hv[d] = H[lb + 8d]
    }

    // ---- sym-0 group stores H_true while it's live ----
    if (isp) {
        float2* hq = (float2*)(out + HT_OFF) + blk * 64;
        #pragma unroll
        for (int d = 0; d < 8; d++) stcs2(hq + lb + 8 * d, Hv[d]);
    }
    if (g == 0) out[NP_OFF] = NOISE_PWR;

    // ---- signal loads (streaming) ----
    const float2* sp = isp ? ((const float2*)pilot_raw + blk * 64)
                           : ((const float2*)x + ((size_t)blk * SS + (sym - 1)) * 64);
    float2 sv[8];
    #pragma unroll
    for (int d = 0; d < 8; d++) sv[d] = ldcs2(sp + lb + 8 * d);

    if (isp) {
        // group-local reduction: mask matches exactly the executing lanes
        float pw = 0.f;
        #pragma unroll
        for (int d = 0; d < 8; d++) pw += sv[d].x * sv[d].x + sv[d].y * sv[d].y;
        pw += __shfl_xor_sync(gmask, pw, 1);
        pw += __shfl_xor_sync(gmask, pw, 2);
        pw += __shfl_xor_sync(gmask, pw, 4);
        float scale = 8.0f * rsqrtf(pw);      // sqrt(PWR/2)/sqrt(mean(pilot_raw^2))
        #pragma unroll
        for (int d = 0; d < 8; d++) { sv[d].x *= scale; sv[d].y *= scale; }
    }

    // ---- fold H*sig in place: Hv dies here, before Nf materializes ----
    #pragma unroll
    for (int d = 0; d < 8; d++) sv[d] = cmul(Hv[d], sv[d]);

    __syncwarp();

    // ---- transpose read + stage 2 ----
    float2 z[8];
    #pragma unroll
    for (int b = 0; b < 8; b++) z[b] = Z[grp][b][lb];
    float2 Nf[8];
    dft8(z, Nf);                              // Nf[d] = N[lb + 8d]

    // ---- epilogue: out = (H*sig) + CNOISE * noiseFFT (streaming stores) ----
    float2* op = isp ? ((float2*)(out + IP_OFF) + blk * 64)
                     : ((float2*)(out + IS_OFF) + ((size_t)blk * SS + (sym - 1)) * 64);
    #pragma unroll
    for (int d = 0; d < 8; d++) {
        float2 r;
        r.x = fmaf(CNOISE, Nf[d].x, sv[d].x);
        r.y = fmaf(CNOISE, Nf[d].y, sv[d].y);
        stcs2(op + lb + 8 * d, r);
    }
}

extern "C" void kernel_launch(void* const* d_in, const int* in_sizes, int n_in,
                              void* d_out, int out_size) {
    const float* x          = (const float*)d_in[0];
    const float* pilot_raw  = (const float*)d_in[1];
    const float* cof_unit   = (const float*)d_in[2];
    const float* noise_unit = (const float*)d_in[3];
    float* out = (float*)d_out;

    ofdm_fused<<<NSYMTOT * 8 / 128, 128>>>(x, pilot_raw, cof_unit, noise_unit, out);
}